// round 3
// baseline (speedup 1.0000x reference)
#include <cuda_runtime.h>
#include <cstdint>

#define BATCH   2
#define LSEQ    2048
#define DM      512
#define NM      32
#define NLAYER  4
#define VOCAB   50257
#define NC      64          // chunks
#define TCH     32          // chunk length = LSEQ/NC (power of 2: 5 squarings)
#define D2      (2*DM)
#define MROWS   (BATCH*LSEQ)   // 4096

// ---------------- scratch (device globals; no mallocs allowed) ----------------
__device__ float g_x   [MROWS*DM];       // residual stream
__device__ float g_y   [MROWS*DM];       // gelu(conv + skip) output
__device__ float g_z   [MROWS*D2];       // projection output
__device__ float g_xln [MROWS*DM];       // layernorm output
__device__ float g_sre [BATCH*NC*NM*DM]; // chunk states / carries (re)
__device__ float g_sim [BATCH*NC*NM*DM]; // chunk states / carries (im)
__device__ float g_abr [NM*DM];          // abar = exp(dt*A)
__device__ float g_abi [NM*DM];
__device__ float g_ctr [NM*DM];          // 2*C*(exp(dtA)-1)/A
__device__ float g_cti [NM*DM];
__device__ int   g_is64;

// ---------------- input_ids dtype sniffing (int32 vs int64) ----------------
__global__ void k_detect(const int* __restrict__ ids) {
    __shared__ int s_any;
    if (threadIdx.x == 0) s_any = 0;
    __syncthreads();
    int any = 0;
    for (int i = threadIdx.x; i < MROWS/2; i += blockDim.x) any |= ids[2*i + 1];
    if (any) atomicOr(&s_any, 1);
    __syncthreads();
    if (threadIdx.x == 0) g_is64 = (s_any == 0) ? 1 : 0;
}

// ---------------- embedding ----------------
__global__ void k_embed(const int* __restrict__ ids,
                        const float* __restrict__ tok,
                        const float* __restrict__ pos) {
    int idx = blockIdx.x * blockDim.x + threadIdx.x;
    if (idx >= MROWS*DM) return;
    int m = idx / DM, d = idx % DM;
    int l = m % LSEQ;
    int t;
    if (g_is64) t = (int)((const long long*)ids)[m];
    else        t = ids[m];
    g_x[idx] = tok[(size_t)t*DM + d] + pos[l*DM + d];
}

// ---------------- S4D discretized coefficients (per layer) ----------------
__global__ void k_coeff(const float* __restrict__ log_dt,
                        const float* __restrict__ C_re,
                        const float* __restrict__ C_im, int layer) {
    int idx = blockIdx.x * blockDim.x + threadIdx.x;   // idx = n*DM + d
    if (idx >= NM*DM) return;
    int n = idx / DM, d = idx % DM;
    float dt  = expf(log_dt[layer*DM + d]);
    const float PI = 3.14159265358979f;
    float aim = PI * (float)n;                         // A = -0.5 + i*pi*n
    float xr = -0.5f * dt, xi = aim * dt;
    float e  = expf(xr);
    float abr = e * cosf(xi), abi = e * sinf(xi);      // abar = exp(dt*A)
    float cr = C_re[(layer*DM + d)*NM + n];
    float ci = C_im[(layer*DM + d)*NM + n];
    float emr = abr - 1.0f, emi = abi;                 // exp(dtA)-1
    float nr = cr*emr - ci*emi;                        // C*(exp(dtA)-1)
    float ni = cr*emi + ci*emr;
    float inv = 2.0f / (0.25f + aim*aim);              // 2/|A|^2 (folds y's 2x)
    g_abr[idx] = abr;  g_abi[idx] = abi;
    g_ctr[idx] = (nr*(-0.5f) + ni*aim) * inv;          // num*conj(A)/|A|^2
    g_cti[idx] = (ni*(-0.5f) - nr*aim) * inv;
}

// ---------------- chunk-local end states S_c ----------------
__global__ void __launch_bounds__(128) k_chunk() {
    int blk = blockIdx.x;                     // b*NC*4 + c*4 + g4
    int g4  = blk & 3;
    int c   = (blk >> 2) % NC;
    int b   = blk / (NC*4);
    int d   = g4*128 + threadIdx.x;

    float ar[NM], ai[NM], sr[NM], si[NM];
#pragma unroll
    for (int n = 0; n < NM; n++) {
        ar[n] = g_abr[n*DM + d]; ai[n] = g_abi[n*DM + d];
        sr[n] = 0.f; si[n] = 0.f;
    }
    const float* xp = g_x + ((size_t)b*LSEQ + c*TCH)*DM + d;
#pragma unroll 4
    for (int t = 0; t < TCH; t++) {
        float u = xp[(size_t)t*DM];
#pragma unroll
        for (int n = 0; n < NM; n++) {
            float nsr = fmaf(ar[n], sr[n], fmaf(-ai[n], si[n], u));
            float nsi = fmaf(ar[n], si[n], ai[n]*sr[n]);
            sr[n] = nsr; si[n] = nsi;
        }
    }
    size_t off = ((size_t)(b*NC + c)*NM)*DM + d;
#pragma unroll
    for (int n = 0; n < NM; n++) {
        g_sre[off + (size_t)n*DM] = sr[n];
        g_sim[off + (size_t)n*DM] = si[n];
    }
}

// ---------------- sequential scan over chunks: S_c -> E_c (in place) ----------------
__global__ void k_scan() {
    int idx = blockIdx.x * blockDim.x + threadIdx.x;   // B*NM*DM
    if (idx >= BATCH*NM*DM) return;
    int d = idx % DM;
    int n = (idx / DM) % NM;
    int b = idx / (NM*DM);
    float pr = g_abr[n*DM + d], pi = g_abi[n*DM + d];
#pragma unroll
    for (int s = 0; s < 5; s++) {                      // abar^(2^5) = abar^TCH
        float t = pr*pr - pi*pi; pi = 2.f*pr*pi; pr = t;
    }
    float er = 0.f, ei = 0.f;
    for (int c = 0; c < NC; c++) {
        size_t off = ((size_t)(b*NC + c)*NM + n)*DM + d;
        float Sr = g_sre[off], Si = g_sim[off];
        g_sre[off] = er; g_sim[off] = ei;              // store carry-in E_c
        float ner = fmaf(pr, er, fmaf(-pi, ei, Sr));
        float nei = fmaf(pr, ei, fmaf( pi, er, Si));
        er = ner; ei = nei;
    }
}

// ---------------- conv output + skip + gelu (recompute recurrence from E_c) ----------------
__global__ void __launch_bounds__(128) k_conv(const float* __restrict__ skipD, int layer) {
    int blk = blockIdx.x;
    int g4  = blk & 3;
    int c   = (blk >> 2) % NC;
    int b   = blk / (NC*4);
    int d   = g4*128 + threadIdx.x;

    float ar[NM], ai[NM], cr[NM], ci[NM], sr[NM], si[NM];
    size_t soff = ((size_t)(b*NC + c)*NM)*DM + d;
#pragma unroll
    for (int n = 0; n < NM; n++) {
        ar[n] = g_abr[n*DM + d]; ai[n] = g_abi[n*DM + d];
        cr[n] = g_ctr[n*DM + d]; ci[n] = g_cti[n*DM + d];
        sr[n] = g_sre[soff + (size_t)n*DM];
        si[n] = g_sim[soff + (size_t)n*DM];
    }
    float sk = skipD[layer*DM + d];
    const float* xp = g_x + ((size_t)b*LSEQ + c*TCH)*DM + d;
    float*       yp = g_y + ((size_t)b*LSEQ + c*TCH)*DM + d;
    for (int t = 0; t < TCH; t++) {
        float u = xp[(size_t)t*DM];
        float acc = 0.f;
#pragma unroll
        for (int n = 0; n < NM; n++) {
            float nsr = fmaf(ar[n], sr[n], fmaf(-ai[n], si[n], u));
            float nsi = fmaf(ar[n], si[n], ai[n]*sr[n]);
            sr[n] = nsr; si[n] = nsi;
            acc = fmaf(cr[n], sr[n], acc);
            acc = fmaf(-ci[n], si[n], acc);
        }
        float yv = fmaf(sk, u, acc);
        // gelu (tanh approx, JAX default)
        float inner = 0.7978845608028654f * fmaf(0.044715f*yv, yv*yv, yv);
        float gv = 0.5f * yv * (1.f + tanhf(inner));
        yp[(size_t)t*DM] = gv;
    }
}

// ---------------- tf32 tensor-core GEMM: C[M,N] = A[M,K] * B[N,K]^T (+bias) ----------------
__device__ __forceinline__ float tf32r(float x) {
    uint32_t u;
    asm("cvt.rna.tf32.f32 %0, %1;" : "=r"(u) : "f"(x));
    return __uint_as_float(u);
}

template<bool HAS_BIAS>
__global__ void __launch_bounds__(256) gemm_tf32(
    const float* __restrict__ A, const float* __restrict__ Bw,
    const float* __restrict__ bias, float* __restrict__ C,
    int M, int N, int K)
{
    __shared__ float As[128][17];
    __shared__ float Bs[64][17];
    const int tid  = threadIdx.x;
    const int m0   = blockIdx.y * 128;
    const int n0   = blockIdx.x * 64;
    const int warp = tid >> 5, lane = tid & 31;
    const int wm = warp & 3;       // m-warp: wm*32
    const int wn = warp >> 2;      // n-warp: wn*32
    const int g  = lane >> 2;      // groupID 0..7
    const int tg = lane & 3;       // thread-in-group 0..3

    float acc[2][4][4];
#pragma unroll
    for (int i = 0; i < 2; i++)
#pragma unroll
        for (int j = 0; j < 4; j++)
#pragma unroll
            for (int r = 0; r < 4; r++) acc[i][j][r] = 0.f;

    const int lrow = tid >> 2;          // 0..63
    const int lcol = (tid & 3) << 2;    // 0,4,8,12

    for (int k0 = 0; k0 < K; k0 += 16) {
#pragma unroll
        for (int h = 0; h < 2; h++) {
            int r = lrow + h*64;
            const float4 v = *reinterpret_cast<const float4*>(A + (size_t)(m0 + r)*K + k0 + lcol);
            As[r][lcol+0] = tf32r(v.x); As[r][lcol+1] = tf32r(v.y);
            As[r][lcol+2] = tf32r(v.z); As[r][lcol+3] = tf32r(v.w);
        }
        {
            float4 v = make_float4(0.f, 0.f, 0.f, 0.f);
            if (n0 + lrow < N)
                v = *reinterpret_cast<const float4*>(Bw + (size_t)(n0 + lrow)*K + k0 + lcol);
            Bs[lrow][lcol+0] = tf32r(v.x); Bs[lrow][lcol+1] = tf32r(v.y);
            Bs[lrow][lcol+2] = tf32r(v.z); Bs[lrow][lcol+3] = tf32r(v.w);
        }
        __syncthreads();
#pragma unroll
        for (int kk = 0; kk < 16; kk += 8) {
            uint32_t af[2][4], bf[4][2];
#pragma unroll
            for (int mf = 0; mf < 2; mf++) {
                int mr = wm*32 + mf*16;
                af[mf][0] = __float_as_uint(As[mr + g    ][kk + tg    ]);
                af[mf][1] = __float_as_uint(As[mr + 8 + g][kk + tg    ]);
                af[mf][2] = __float_as_uint(As[mr + g    ][kk + tg + 4]);
                af[mf][3] = __float_as_uint(As[mr + 8 + g][kk + tg + 4]);
            }
#pragma unroll
            for (int nf = 0; nf < 4; nf++) {
                int nc = wn*32 + nf*8;
                bf[nf][0] = __float_as_uint(Bs[nc + g][kk + tg    ]);
                bf[nf][1] = __float_as_uint(Bs[nc + g][kk + tg + 4]);
            }
#pragma unroll
            for (int mf = 0; mf < 2; mf++)
#pragma unroll
                for (int nf = 0; nf < 4; nf++)
                    asm volatile(
                        "mma.sync.aligned.m16n8k8.row.col.f32.tf32.tf32.f32 "
                        "{%0,%1,%2,%3}, {%4,%5,%6,%7}, {%8,%9}, {%0,%1,%2,%3};\n"
                        : "+f"(acc[mf][nf][0]), "+f"(acc[mf][nf][1]),
                          "+f"(acc[mf][nf][2]), "+f"(acc[mf][nf][3])
                        : "r"(af[mf][0]), "r"(af[mf][1]), "r"(af[mf][2]), "r"(af[mf][3]),
                          "r"(bf[nf][0]), "r"(bf[nf][1]));
        }
        __syncthreads();
    }
    // epilogue
#pragma unroll
    for (int mf = 0; mf < 2; mf++) {
        int row = m0 + wm*32 + mf*16 + g;
#pragma unroll
        for (int nf = 0; nf < 4; nf++) {
            int col = n0 + wn*32 + nf*8 + tg*2;
            if (col < N) {
                float bv = HAS_BIAS ? bias[col] : 0.f;
                C[(size_t)row*N + col]     = acc[mf][nf][0] + bv;
                C[(size_t)(row+8)*N + col] = acc[mf][nf][2] + bv;
            }
            if (col + 1 < N) {
                float bv = HAS_BIAS ? bias[col+1] : 0.f;
                C[(size_t)row*N + col + 1]     = acc[mf][nf][1] + bv;
                C[(size_t)(row+8)*N + col + 1] = acc[mf][nf][3] + bv;
            }
        }
    }
}

// ---------------- GLU + residual ----------------
__global__ void k_glu() {
    int idx = blockIdx.x * blockDim.x + threadIdx.x;
    if (idx >= MROWS*DM) return;
    int m = idx / DM, d = idx % DM;
    float z1 = g_z[(size_t)m*D2 + d];
    float z2 = g_z[(size_t)m*D2 + DM + d];
    float sg = 1.f / (1.f + expf(-z2));
    g_x[idx] += z1 * sg;
}

// ---------------- final layernorm ----------------
__global__ void __launch_bounds__(128) k_ln(const float* __restrict__ gw,
                                            const float* __restrict__ bw) {
    __shared__ float red[8];
    int m = blockIdx.x, tid = threadIdx.x;
    const float* xr = g_x + (size_t)m*DM;
    float v0 = xr[tid], v1 = xr[tid+128], v2 = xr[tid+256], v3 = xr[tid+384];
    float s = v0+v1+v2+v3;
    float q = v0*v0+v1*v1+v2*v2+v3*v3;
#pragma unroll
    for (int o = 16; o > 0; o >>= 1) {
        s += __shfl_down_sync(0xffffffffu, s, o);
        q += __shfl_down_sync(0xffffffffu, q, o);
    }
    if ((tid & 31) == 0) { red[tid>>5] = s; red[4 + (tid>>5)] = q; }
    __syncthreads();
    if (tid == 0) {
        red[0] = red[0]+red[1]+red[2]+red[3];
        red[4] = red[4]+red[5]+red[6]+red[7];
    }
    __syncthreads();
    float mu  = red[0] * (1.f/DM);
    float var = red[4] * (1.f/DM) - mu*mu;
    float inv = rsqrtf(var + 1e-5f);
    float* o = g_xln + (size_t)m*DM;
    o[tid]     = (v0-mu)*inv*gw[tid]     + bw[tid];
    o[tid+128] = (v1-mu)*inv*gw[tid+128] + bw[tid+128];
    o[tid+256] = (v2-mu)*inv*gw[tid+256] + bw[tid+256];
    o[tid+384] = (v3-mu)*inv*gw[tid+384] + bw[tid+384];
}

// ---------------- host launcher ----------------
extern "C" void kernel_launch(void* const* d_in, const int* in_sizes, int n_in,
                              void* d_out, int out_size) {
    const int*   ids   = (const int*)  d_in[0];
    const float* tok   = (const float*)d_in[1];
    const float* pos   = (const float*)d_in[2];
    const float* logdt = (const float*)d_in[3];
    const float* cre   = (const float*)d_in[4];
    const float* cim   = (const float*)d_in[5];
    const float* skp   = (const float*)d_in[6];
    const float* outw  = (const float*)d_in[7];
    const float* outb  = (const float*)d_in[8];
    const float* lng   = (const float*)d_in[9];
    const float* lnb   = (const float*)d_in[10];
    const float* headw = (const float*)d_in[11];
    float* out = (float*)d_out;

    float *py, *pz, *pxln;
    cudaGetSymbolAddress((void**)&py,   g_y);
    cudaGetSymbolAddress((void**)&pz,   g_z);
    cudaGetSymbolAddress((void**)&pxln, g_xln);

    k_detect<<<1, 256>>>(ids);
    k_embed<<<(MROWS*DM)/256, 256>>>(ids, tok, pos);

    for (int i = 0; i < NLAYER; i++) {
        k_coeff<<<(NM*DM)/256, 256>>>(logdt, cre, cim, i);
        k_chunk<<<BATCH*NC*4, 128>>>();
        k_scan<<<(BATCH*NM*DM)/256, 256>>>();
        k_conv<<<BATCH*NC*4, 128>>>(skp, i);
        dim3 gp(D2/64, MROWS/128);
        gemm_tf32<true><<<gp, 256>>>(py, outw + (size_t)i*D2*DM, outb + i*D2,
                                     pz, MROWS, D2, DM);
        k_glu<<<(MROWS*DM)/256, 256>>>();
    }

    k_ln<<<MROWS, 128>>>(lng, lnb);
    dim3 gh((VOCAB + 63)/64, MROWS/128);
    gemm_tf32<false><<<gh, 256>>>(pxln, headw, nullptr, out, MROWS, VOCAB, DM);
}

// round 5
// speedup vs baseline: 1.7059x; 1.7059x over previous
#include <cuda_runtime.h>
#include <cstdint>

#define BATCH   2
#define LSEQ    2048
#define DM      512
#define NM      32
#define NLAYER  4
#define VOCAB   50257
#define NC      64          // chunks
#define TCH     32          // chunk length = LSEQ/NC
#define D2      (2*DM)
#define MROWS   (BATCH*LSEQ)   // 4096

// ---------------- scratch (device globals; no mallocs allowed) ----------------
__device__ float g_x   [MROWS*DM];
__device__ float g_y   [MROWS*DM];
__device__ float g_z   [MROWS*D2];
__device__ float g_xln [MROWS*DM];
__device__ float g_sre [BATCH*NC*NM*DM];
__device__ float g_sim [BATCH*NC*NM*DM];
__device__ float g_abr [NM*DM];
__device__ float g_abi [NM*DM];
__device__ float g_ctr [NM*DM];
__device__ float g_cti [NM*DM];
__device__ int   g_is64;

// ---------------- input_ids dtype sniffing (int32 vs int64) ----------------
__global__ void k_detect(const int* __restrict__ ids) {
    __shared__ int s_any;
    if (threadIdx.x == 0) s_any = 0;
    __syncthreads();
    int any = 0;
    for (int i = threadIdx.x; i < MROWS/2; i += blockDim.x) any |= ids[2*i + 1];
    if (any) atomicOr(&s_any, 1);
    __syncthreads();
    if (threadIdx.x == 0) g_is64 = (s_any == 0) ? 1 : 0;
}

// ---------------- embedding ----------------
__global__ void k_embed(const int* __restrict__ ids,
                        const float* __restrict__ tok,
                        const float* __restrict__ pos) {
    int idx = blockIdx.x * blockDim.x + threadIdx.x;
    if (idx >= MROWS*DM) return;
    int m = idx / DM, d = idx % DM;
    int l = m % LSEQ;
    int t;
    if (g_is64) t = (int)((const long long*)ids)[m];
    else        t = ids[m];
    g_x[idx] = tok[(size_t)t*DM + d] + pos[l*DM + d];
}

// ---------------- S4D discretized coefficients (per layer) ----------------
__global__ void k_coeff(const float* __restrict__ log_dt,
                        const float* __restrict__ C_re,
                        const float* __restrict__ C_im, int layer) {
    int idx = blockIdx.x * blockDim.x + threadIdx.x;   // idx = n*DM + d
    if (idx >= NM*DM) return;
    int n = idx / DM, d = idx % DM;
    float dt  = expf(log_dt[layer*DM + d]);
    const float PI = 3.14159265358979f;
    float aim = PI * (float)n;                         // A = -0.5 + i*pi*n
    float xr = -0.5f * dt, xi = aim * dt;
    float e  = expf(xr);
    float abr = e * cosf(xi), abi = e * sinf(xi);      // abar = exp(dt*A)
    float cr = C_re[(layer*DM + d)*NM + n];
    float ci = C_im[(layer*DM + d)*NM + n];
    float emr = abr - 1.0f, emi = abi;                 // exp(dtA)-1
    float nr = cr*emr - ci*emi;
    float ni = cr*emi + ci*emr;
    float inv = 2.0f / (0.25f + aim*aim);
    g_abr[idx] = abr;  g_abi[idx] = abi;
    g_ctr[idx] = (nr*(-0.5f) + ni*aim) * inv;
    g_cti[idx] = (ni*(-0.5f) - nr*aim) * inv;
}

// ---------------- chunk-local end states S_c ----------------
__global__ void __launch_bounds__(128) k_chunk() {
    int blk = blockIdx.x;
    int g4  = blk & 3;
    int c   = (blk >> 2) % NC;
    int b   = blk / (NC*4);
    int d   = g4*128 + threadIdx.x;

    float ar[NM], ai[NM], sr[NM], si[NM];
#pragma unroll
    for (int n = 0; n < NM; n++) {
        ar[n] = g_abr[n*DM + d]; ai[n] = g_abi[n*DM + d];
        sr[n] = 0.f; si[n] = 0.f;
    }
    const float* xp = g_x + ((size_t)b*LSEQ + c*TCH)*DM + d;
#pragma unroll 4
    for (int t = 0; t < TCH; t++) {
        float u = xp[(size_t)t*DM];
#pragma unroll
        for (int n = 0; n < NM; n++) {
            float nsr = fmaf(ar[n], sr[n], fmaf(-ai[n], si[n], u));
            float nsi = fmaf(ar[n], si[n], ai[n]*sr[n]);
            sr[n] = nsr; si[n] = nsi;
        }
    }
    size_t off = ((size_t)(b*NC + c)*NM)*DM + d;
#pragma unroll
    for (int n = 0; n < NM; n++) {
        g_sre[off + (size_t)n*DM] = sr[n];
        g_sim[off + (size_t)n*DM] = si[n];
    }
}

// ---------------- sequential scan over chunks: S_c -> E_c (in place) ----------------
__global__ void k_scan() {
    int idx = blockIdx.x * blockDim.x + threadIdx.x;
    if (idx >= BATCH*NM*DM) return;
    int d = idx % DM;
    int n = (idx / DM) % NM;
    int b = idx / (NM*DM);
    float pr = g_abr[n*DM + d], pi = g_abi[n*DM + d];
#pragma unroll
    for (int s = 0; s < 5; s++) {
        float t = pr*pr - pi*pi; pi = 2.f*pr*pi; pr = t;
    }
    float er = 0.f, ei = 0.f;
    for (int c = 0; c < NC; c++) {
        size_t off = ((size_t)(b*NC + c)*NM + n)*DM + d;
        float Sr = g_sre[off], Si = g_sim[off];
        g_sre[off] = er; g_sim[off] = ei;
        float ner = fmaf(pr, er, fmaf(-pi, ei, Sr));
        float nei = fmaf(pr, ei, fmaf( pi, er, Si));
        er = ner; ei = nei;
    }
}

// ---------------- conv output + skip + gelu ----------------
__global__ void __launch_bounds__(128) k_conv(const float* __restrict__ skipD, int layer) {
    int blk = blockIdx.x;
    int g4  = blk & 3;
    int c   = (blk >> 2) % NC;
    int b   = blk / (NC*4);
    int d   = g4*128 + threadIdx.x;

    float ar[NM], ai[NM], cr[NM], ci[NM], sr[NM], si[NM];
    size_t soff = ((size_t)(b*NC + c)*NM)*DM + d;
#pragma unroll
    for (int n = 0; n < NM; n++) {
        ar[n] = g_abr[n*DM + d]; ai[n] = g_abi[n*DM + d];
        cr[n] = g_ctr[n*DM + d]; ci[n] = g_cti[n*DM + d];
        sr[n] = g_sre[soff + (size_t)n*DM];
        si[n] = g_sim[soff + (size_t)n*DM];
    }
    float sk = skipD[layer*DM + d];
    const float* xp = g_x + ((size_t)b*LSEQ + c*TCH)*DM + d;
    float*       yp = g_y + ((size_t)b*LSEQ + c*TCH)*DM + d;
    for (int t = 0; t < TCH; t++) {
        float u = xp[(size_t)t*DM];
        float acc = 0.f;
#pragma unroll
        for (int n = 0; n < NM; n++) {
            float nsr = fmaf(ar[n], sr[n], fmaf(-ai[n], si[n], u));
            float nsi = fmaf(ar[n], si[n], ai[n]*sr[n]);
            sr[n] = nsr; si[n] = nsi;
            acc = fmaf(cr[n], sr[n], acc);
            acc = fmaf(-ci[n], si[n], acc);
        }
        float yv = fmaf(sk, u, acc);
        float inner = 0.7978845608028654f * fmaf(0.044715f*yv, yv*yv, yv);
        float gv = 0.5f * yv * (1.f + tanhf(inner));
        yp[(size_t)t*DM] = gv;
    }
}

// ---------------- pipelined tf32 tensor-core GEMM ----------------
// C[M,N] = A[M,K] * B[N,K]^T (+bias).  128x128 block tile, BK=32,
// 2-stage cp.async double buffer, 8 warps (4x2), warp tile 32x64.
__device__ __forceinline__ uint32_t tf32u(float x) {
    uint32_t u;
    asm("cvt.rna.tf32.f32 %0, %1;" : "=r"(u) : "f"(x));
    return u;
}

#define GLDA 36   // smem leading dim (pad: stride 144B keeps 16B align, kills conflicts)

template<bool HAS_BIAS>
__global__ void __launch_bounds__(256, 2) gemm_tf32_pipe(
    const float* __restrict__ A, const float* __restrict__ Bw,
    const float* __restrict__ bias, float* __restrict__ C,
    int M, int N, int K)
{
    extern __shared__ float smem[];
    float* As = smem;                    // [2][128][GLDA]
    float* Bs = smem + 2*128*GLDA;       // [2][128][GLDA]

    const int tid  = threadIdx.x;
    const int m0   = blockIdx.y * 128;
    const int n0   = blockIdx.x * 128;
    const int warp = tid >> 5, lane = tid & 31;
    const int wm = warp & 3;             // row-warp: wm*32
    const int wn = warp >> 2;            // col-warp: wn*64
    const int g  = lane >> 2;            // 0..7
    const int tg = lane & 3;             // 0..3

    float acc[2][8][4];
#pragma unroll
    for (int i = 0; i < 2; i++)
#pragma unroll
        for (int j = 0; j < 8; j++)
#pragma unroll
            for (int r = 0; r < 4; r++) acc[i][j][r] = 0.f;

    const int lr = tid >> 3;            // 0..31  (row within 32-row slab)
    const int lc = (tid & 7) << 2;      // 0,4,...,28

    const float* Abase = A  + (size_t)m0 * K + lc;
    const float* Bbase = Bw + lc;

    const int T = K / 32;               // 16 stages for K=512

    // ---- async tile loader ----
    auto issue = [&](int t, int buf) {
        float* as = As + buf*128*GLDA;
        const float* Ap = Abase + t*32;
#pragma unroll
        for (int h = 0; h < 4; h++) {
            int r = h*32 + lr;
            uint32_t da = (uint32_t)__cvta_generic_to_shared(as + r*GLDA + lc);
            asm volatile("cp.async.ca.shared.global [%0], [%1], 16;\n"
                         :: "r"(da), "l"(Ap + (size_t)r * K));
        }
        float* bs = Bs + buf*128*GLDA;
        const float* Bp = Bbase + t*32;
#pragma unroll
        for (int h = 0; h < 4; h++) {
            int r = h*32 + lr;
            int gr = n0 + r;
            uint32_t da = (uint32_t)__cvta_generic_to_shared(bs + r*GLDA + lc);
            int sz = (gr < N) ? 16 : 0;     // zero-fill OOB rows
            asm volatile("cp.async.ca.shared.global [%0], [%1], 16, %2;\n"
                         :: "r"(da), "l"(Bp + (size_t)gr * K), "r"(sz));
        }
        asm volatile("cp.async.commit_group;\n");
    };

    auto compute = [&](int buf) {
        const float* as = As + buf*128*GLDA;
        const float* bs = Bs + buf*128*GLDA;
#pragma unroll
        for (int kk = 0; kk < 32; kk += 8) {
            uint32_t af[2][4], bf[8][2];
#pragma unroll
            for (int mf = 0; mf < 2; mf++) {
                int mr = wm*32 + mf*16;
                af[mf][0] = tf32u(as[(mr + g    )*GLDA + kk + tg    ]);
                af[mf][1] = tf32u(as[(mr + 8 + g)*GLDA + kk + tg    ]);
                af[mf][2] = tf32u(as[(mr + g    )*GLDA + kk + tg + 4]);
                af[mf][3] = tf32u(as[(mr + 8 + g)*GLDA + kk + tg + 4]);
            }
#pragma unroll
            for (int nf = 0; nf < 8; nf++) {
                int nc = wn*64 + nf*8;
                bf[nf][0] = tf32u(bs[(nc + g)*GLDA + kk + tg    ]);
                bf[nf][1] = tf32u(bs[(nc + g)*GLDA + kk + tg + 4]);
            }
#pragma unroll
            for (int mf = 0; mf < 2; mf++)
#pragma unroll
                for (int nf = 0; nf < 8; nf++)
                    asm volatile(
                        "mma.sync.aligned.m16n8k8.row.col.f32.tf32.tf32.f32 "
                        "{%0,%1,%2,%3}, {%4,%5,%6,%7}, {%8,%9}, {%0,%1,%2,%3};\n"
                        : "+f"(acc[mf][nf][0]), "+f"(acc[mf][nf][1]),
                          "+f"(acc[mf][nf][2]), "+f"(acc[mf][nf][3])
                        : "r"(af[mf][0]), "r"(af[mf][1]), "r"(af[mf][2]), "r"(af[mf][3]),
                          "r"(bf[nf][0]), "r"(bf[nf][1]));
        }
    };

    issue(0, 0);
    for (int t = 0; t < T; t++) {
        if (t + 1 < T) {
            issue(t + 1, (t + 1) & 1);
            asm volatile("cp.async.wait_group 1;\n");
        } else {
            asm volatile("cp.async.wait_group 0;\n");
        }
        __syncthreads();
        compute(t & 1);
        __syncthreads();
    }

    // ---- epilogue (SCALAR stores: N=50257 is odd, row*N+col can be 4B-aligned only) ----
#pragma unroll
    for (int mf = 0; mf < 2; mf++) {
        int row = m0 + wm*32 + mf*16 + g;
#pragma unroll
        for (int nf = 0; nf < 8; nf++) {
            int col = n0 + wn*64 + nf*8 + tg*2;
            if (col < N) {
                float b0 = HAS_BIAS ? bias[col] : 0.f;
                C[(size_t)row*N + col]     = acc[mf][nf][0] + b0;
                C[(size_t)(row+8)*N + col] = acc[mf][nf][2] + b0;
            }
            if (col + 1 < N) {
                float b1 = HAS_BIAS ? bias[col + 1] : 0.f;
                C[(size_t)row*N + col + 1]     = acc[mf][nf][1] + b1;
                C[(size_t)(row+8)*N + col + 1] = acc[mf][nf][3] + b1;
            }
        }
    }
}

// ---------------- GLU + residual ----------------
__global__ void k_glu() {
    int idx = blockIdx.x * blockDim.x + threadIdx.x;
    if (idx >= MROWS*DM) return;
    int m = idx / DM, d = idx % DM;
    float z1 = g_z[(size_t)m*D2 + d];
    float z2 = g_z[(size_t)m*D2 + DM + d];
    float sg = 1.f / (1.f + expf(-z2));
    g_x[idx] += z1 * sg;
}

// ---------------- final layernorm ----------------
__global__ void __launch_bounds__(128) k_ln(const float* __restrict__ gw,
                                            const float* __restrict__ bw) {
    __shared__ float red[8];
    int m = blockIdx.x, tid = threadIdx.x;
    const float* xr = g_x + (size_t)m*DM;
    float v0 = xr[tid], v1 = xr[tid+128], v2 = xr[tid+256], v3 = xr[tid+384];
    float s = v0+v1+v2+v3;
    float q = v0*v0+v1*v1+v2*v2+v3*v3;
#pragma unroll
    for (int o = 16; o > 0; o >>= 1) {
        s += __shfl_down_sync(0xffffffffu, s, o);
        q += __shfl_down_sync(0xffffffffu, q, o);
    }
    if ((tid & 31) == 0) { red[tid>>5] = s; red[4 + (tid>>5)] = q; }
    __syncthreads();
    if (tid == 0) {
        red[0] = red[0]+red[1]+red[2]+red[3];
        red[4] = red[4]+red[5]+red[6]+red[7];
    }
    __syncthreads();
    float mu  = red[0] * (1.f/DM);
    float var = red[4] * (1.f/DM) - mu*mu;
    float inv = rsqrtf(var + 1e-5f);
    float* o = g_xln + (size_t)m*DM;
    o[tid]     = (v0-mu)*inv*gw[tid]     + bw[tid];
    o[tid+128] = (v1-mu)*inv*gw[tid+128] + bw[tid+128];
    o[tid+256] = (v2-mu)*inv*gw[tid+256] + bw[tid+256];
    o[tid+384] = (v3-mu)*inv*gw[tid+384] + bw[tid+384];
}

// ---------------- host launcher ----------------
extern "C" void kernel_launch(void* const* d_in, const int* in_sizes, int n_in,
                              void* d_out, int out_size) {
    const int*   ids   = (const int*)  d_in[0];
    const float* tok   = (const float*)d_in[1];
    const float* pos   = (const float*)d_in[2];
    const float* logdt = (const float*)d_in[3];
    const float* cre   = (const float*)d_in[4];
    const float* cim   = (const float*)d_in[5];
    const float* skp   = (const float*)d_in[6];
    const float* outw  = (const float*)d_in[7];
    const float* outb  = (const float*)d_in[8];
    const float* lng   = (const float*)d_in[9];
    const float* lnb   = (const float*)d_in[10];
    const float* headw = (const float*)d_in[11];
    float* out = (float*)d_out;

    float *py, *pz, *pxln;
    cudaGetSymbolAddress((void**)&py,   g_y);
    cudaGetSymbolAddress((void**)&pz,   g_z);
    cudaGetSymbolAddress((void**)&pxln, g_xln);

    const int SMEM_GEMM = 2 * 128 * GLDA * 4 * 2;   // 73728 B
    static int cfg_done = 0;
    if (!cfg_done) {
        cudaFuncSetAttribute(gemm_tf32_pipe<true>,
                             cudaFuncAttributeMaxDynamicSharedMemorySize, SMEM_GEMM);
        cudaFuncSetAttribute(gemm_tf32_pipe<false>,
                             cudaFuncAttributeMaxDynamicSharedMemorySize, SMEM_GEMM);
        cfg_done = 1;
    }

    k_detect<<<1, 256>>>(ids);
    k_embed<<<(MROWS*DM)/256, 256>>>(ids, tok, pos);

    for (int i = 0; i < NLAYER; i++) {
        k_coeff<<<(NM*DM)/256, 256>>>(logdt, cre, cim, i);
        k_chunk<<<BATCH*NC*4, 128>>>();
        k_scan<<<(BATCH*NM*DM)/256, 256>>>();
        k_conv<<<BATCH*NC*4, 128>>>(skp, i);
        dim3 gp(D2/128, MROWS/128);
        gemm_tf32_pipe<true><<<gp, 256, SMEM_GEMM>>>(
            py, outw + (size_t)i*D2*DM, outb + i*D2, pz, MROWS, D2, DM);
        k_glu<<<(MROWS*DM)/256, 256>>>();
    }

    k_ln<<<MROWS, 128>>>(lng, lnb);
    dim3 gh((VOCAB + 127)/128, MROWS/128);
    gemm_tf32_pipe<false><<<gh, 256, SMEM_GEMM>>>(
        pxln, headw, nullptr, out, MROWS, VOCAB, DM);
}